// round 1
// baseline (speedup 1.0000x reference)
#include <cuda_runtime.h>
#include <math.h>

#define HD    1024
#define KH    8
#define BATCH 8192
#define EPSLN 1e-5f

// ---------------- scratch (static device globals; no allocs allowed) --------
static __device__ float g_y1[(size_t)BATCH * 2 * HD];   //  64 MB : x@W1+b1 -> ln/relu in place
static __device__ float g_xe[(size_t)BATCH * HD];       //  32 MB : x@We1_top + be1
static __device__ float g_e [(size_t)BATCH * KH * HD];  // 256 MB : pre-LN evaluator activations

// ---------------- 128x128x16 fp32 GEMM, 256 thr, 8x8 per thread -------------
// C[M,N] = A[M,Kd] @ W[Kd,N] (+ bias[n]) (+ addv[row>>3][n] if ADD_BCAST)
template<bool ADD_BCAST>
__global__ void __launch_bounds__(256, 2) sgemm128(
    const float* __restrict__ A, const float* __restrict__ Wm,
    const float* __restrict__ bias, const float* __restrict__ addv,
    float* __restrict__ C, int M, int N, int Kd)
{
    __shared__ float As[16][128];   // A tile, transposed (k-major)
    __shared__ float Bs[16][128];

    const int bn  = blockIdx.x * 128;
    const int bm  = blockIdx.y * 128;
    const int tid = threadIdx.x;
    const int tx  = tid & 15;       // 16 cols of threads
    const int ty  = tid >> 4;       // 16 rows of threads

    float acc[8][8];
    #pragma unroll
    for (int i = 0; i < 8; i++)
        #pragma unroll
        for (int j = 0; j < 8; j++) acc[i][j] = 0.f;

    const float* Aptr = A  + (size_t)bm * Kd;
    const float* Bptr = Wm + bn;

    const int arow = tid >> 2;          // 0..63 (two passes -> 128 rows)
    const int acol = (tid & 3) * 4;     // 0,4,8,12
    const int brow = tid >> 5;          // 0..7 (two passes -> 16 rows)
    const int bcol = (tid & 31) * 4;    // 0..124

    for (int k0 = 0; k0 < Kd; k0 += 16) {
        #pragma unroll
        for (int i = 0; i < 2; i++) {
            int r = arow + i * 64;
            float4 v = *(const float4*)(Aptr + (size_t)r * Kd + k0 + acol);
            As[acol + 0][r] = v.x;
            As[acol + 1][r] = v.y;
            As[acol + 2][r] = v.z;
            As[acol + 3][r] = v.w;
        }
        #pragma unroll
        for (int i = 0; i < 2; i++) {
            int r = brow + i * 8;
            float4 v = *(const float4*)(Bptr + (size_t)(k0 + r) * N + bcol);
            *(float4*)&Bs[r][bcol] = v;
        }
        __syncthreads();

        #pragma unroll
        for (int kk = 0; kk < 16; kk++) {
            float ra[8], rb[8];
            *(float4*)&ra[0] = *(const float4*)&As[kk][ty * 4];
            *(float4*)&ra[4] = *(const float4*)&As[kk][64 + ty * 4];
            *(float4*)&rb[0] = *(const float4*)&Bs[kk][tx * 4];
            *(float4*)&rb[4] = *(const float4*)&Bs[kk][64 + tx * 4];
            #pragma unroll
            for (int i = 0; i < 8; i++)
                #pragma unroll
                for (int j = 0; j < 8; j++)
                    acc[i][j] = fmaf(ra[i], rb[j], acc[i][j]);
        }
        __syncthreads();
    }

    // epilogue: two 4-row quads x two 4-col quads
    #pragma unroll
    for (int iq = 0; iq < 2; iq++) {
        #pragma unroll
        for (int ii = 0; ii < 4; ii++) {
            int rm = bm + iq * 64 + ty * 4 + ii;
            float* crow = C + (size_t)rm * N;
            const float* arow2 = ADD_BCAST ? (addv + (size_t)(rm >> 3) * N) : nullptr;
            #pragma unroll
            for (int jq = 0; jq < 2; jq++) {
                int cn = bn + jq * 64 + tx * 4;
                float4 v;
                float o0 = acc[iq * 4 + ii][jq * 4 + 0];
                float o1 = acc[iq * 4 + ii][jq * 4 + 1];
                float o2 = acc[iq * 4 + ii][jq * 4 + 2];
                float o3 = acc[iq * 4 + ii][jq * 4 + 3];
                if (bias) {
                    o0 += bias[cn + 0]; o1 += bias[cn + 1];
                    o2 += bias[cn + 2]; o3 += bias[cn + 3];
                }
                if (ADD_BCAST) {
                    o0 += arow2[cn + 0]; o1 += arow2[cn + 1];
                    o2 += arow2[cn + 2]; o3 += arow2[cn + 3];
                }
                v.x = o0; v.y = o1; v.z = o2; v.w = o3;
                *(float4*)(crow + cn) = v;
            }
        }
    }
}

// ---------------- block reduction of two scalars (256 threads) --------------
__device__ __forceinline__ void block_reduce2(float& a, float& b) {
    __shared__ float sa[8], sb[8];
    float x = a, y = b;
    #pragma unroll
    for (int o = 16; o > 0; o >>= 1) {
        x += __shfl_down_sync(0xffffffffu, x, o);
        y += __shfl_down_sync(0xffffffffu, y, o);
    }
    int w = threadIdx.x >> 5;
    if ((threadIdx.x & 31) == 0) { sa[w] = x; sb[w] = y; }
    __syncthreads();
    if (threadIdx.x == 0) {
        float xs = 0.f, ys = 0.f;
        #pragma unroll
        for (int i = 0; i < 8; i++) { xs += sa[i]; ys += sb[i]; }
        sa[0] = xs; sb[0] = ys;
    }
    __syncthreads();
    a = sa[0]; b = sb[0];
    __syncthreads();
}

// ---------------- LN + ReLU in place over width 2048 ------------------------
__global__ void __launch_bounds__(256) ln_relu_2048(
    float* __restrict__ y, const float* __restrict__ g, const float* __restrict__ beta)
{
    const int row = blockIdx.x;
    float* p = y + (size_t)row * 2048;
    const int t = threadIdx.x;
    float v[8];
    float s = 0.f, ss = 0.f;
    #pragma unroll
    for (int i = 0; i < 8; i++) {
        v[i] = p[t + i * 256];
        s += v[i]; ss += v[i] * v[i];
    }
    block_reduce2(s, ss);
    const float mean = s * (1.f / 2048.f);
    const float var  = ss * (1.f / 2048.f) - mean * mean;
    const float rs   = rsqrtf(var + EPSLN);
    #pragma unroll
    for (int i = 0; i < 8; i++) {
        int j = t + i * 256;
        float o = (v[i] - mean) * rs * g[j] + beta[j];
        p[j] = fmaxf(o, 0.f);
    }
}

// ---------------- per-(b,k) row: LN + ReLU + dot(We2) + sigmoid -------------
__global__ void __launch_bounds__(256) score_kernel(
    const float* __restrict__ e, const float* __restrict__ ge,
    const float* __restrict__ betae, const float* __restrict__ We2,
    const float* __restrict__ be2, float* __restrict__ scores)
{
    const int row = blockIdx.x;             // 0 .. B*K-1
    const float* p = e + (size_t)row * HD;
    const int t = threadIdx.x;
    float v[4];
    float s = 0.f, ss = 0.f;
    #pragma unroll
    for (int i = 0; i < 4; i++) {
        v[i] = p[t + i * 256];
        s += v[i]; ss += v[i] * v[i];
    }
    block_reduce2(s, ss);
    const float mean = s * (1.f / 1024.f);
    const float var  = ss * (1.f / 1024.f) - mean * mean;
    const float rs   = rsqrtf(var + EPSLN);
    float d = 0.f, dummy = 0.f;
    #pragma unroll
    for (int i = 0; i < 4; i++) {
        int j = t + i * 256;
        float o = fmaxf((v[i] - mean) * rs * ge[j] + betae[j], 0.f);
        d = fmaf(o, We2[j], d);
    }
    block_reduce2(d, dummy);
    if (t == 0) scores[row] = 1.f / (1.f + expf(-(d + be2[0])));
}

// ---------------- argmax over K, gather best hypothesis ---------------------
__global__ void __launch_bounds__(128) finalize_kernel(
    const float* __restrict__ scores, const float* __restrict__ hyps,
    float* __restrict__ best_hyp, float* __restrict__ best_idx,
    float* __restrict__ best_sc)
{
    const int b = blockIdx.x;
    __shared__ int sidx;
    if (threadIdx.x == 0) {
        const float* sc = scores + (size_t)b * KH;
        int bi = 0; float bv = sc[0];
        #pragma unroll
        for (int k = 1; k < KH; k++)
            if (sc[k] > bv) { bv = sc[k]; bi = k; }   // strict > keeps first max (jnp.argmax)
        sidx = bi;
        best_idx[b] = (float)bi;
        best_sc[b]  = bv;
    }
    __syncthreads();
    const float* src = hyps + ((size_t)b * KH + sidx) * HD;
    float* dst = best_hyp + (size_t)b * HD;
    #pragma unroll
    for (int i = 0; i < HD / 128; i++)
        dst[threadIdx.x + i * 128] = src[threadIdx.x + i * 128];
}

// ---------------- launcher ---------------------------------------------------
extern "C" void kernel_launch(void* const* d_in, const int* in_sizes, int n_in,
                              void* d_out, int out_size)
{
    const float* x     = (const float*)d_in[0];
    const float* W1    = (const float*)d_in[1];
    const float* b1    = (const float*)d_in[2];
    const float* g1    = (const float*)d_in[3];
    const float* beta1 = (const float*)d_in[4];
    const float* W2    = (const float*)d_in[5];
    const float* b2    = (const float*)d_in[6];
    const float* We1   = (const float*)d_in[7];
    const float* be1   = (const float*)d_in[8];
    const float* ge    = (const float*)d_in[9];
    const float* betae = (const float*)d_in[10];
    const float* We2   = (const float*)d_in[11];
    const float* be2   = (const float*)d_in[12];

    float* out = (float*)d_out;
    float* out_best_hyp = out;                                        // [B, H]
    float* out_hyps     = out + (size_t)BATCH * HD;                   // [B, K, H]
    float* out_scores   = out_hyps + (size_t)BATCH * KH * HD;         // [B, K]
    float* out_best_idx = out_scores + (size_t)BATCH * KH;            // [B, 1]
    float* out_best_sc  = out_best_idx + BATCH;                       // [B, 1]

    float *y1, *xe, *e;
    cudaGetSymbolAddress((void**)&y1, g_y1);
    cudaGetSymbolAddress((void**)&xe, g_xe);
    cudaGetSymbolAddress((void**)&e,  g_e);

    // G1: y1 = x @ W1 + b1                         [8192, 2048]
    sgemm128<false><<<dim3(2 * HD / 128, BATCH / 128), 256>>>(
        x, W1, b1, nullptr, y1, BATCH, 2 * HD, HD);

    // GX: xe = x @ We1[0:H,:] + be1                [8192, 1024]  (shared across K)
    sgemm128<false><<<dim3(HD / 128, BATCH / 128), 256>>>(
        x, We1, be1, nullptr, xe, BATCH, HD, HD);

    // LN + ReLU over width 2048, in place
    ln_relu_2048<<<BATCH, 256>>>(y1, g1, beta1);

    // G2: hyps = h @ W2 + b2                       [8192, 8192] -> d_out hyps region
    sgemm128<false><<<dim3(KH * HD / 128, BATCH / 128), 256>>>(
        y1, W2, b2, nullptr, out_hyps, BATCH, KH * HD, 2 * HD);

    // G3: e = hyps(view [B*K, H]) @ We1[H:2H,:] + xe[b]   [65536, 1024]
    sgemm128<true><<<dim3(HD / 128, BATCH * KH / 128), 256>>>(
        out_hyps, We1 + (size_t)HD * HD, nullptr, xe, e, BATCH * KH, HD, HD);

    // scores = sigmoid(relu(LN(e)) . We2 + be2)    [B, K]
    score_kernel<<<BATCH * KH, 256>>>(e, ge, betae, We2, be2, out_scores);

    // argmax / gather
    finalize_kernel<<<BATCH, 128>>>(out_scores, out_hyps,
                                    out_best_hyp, out_best_idx, out_best_sc);
}

// round 2
// speedup vs baseline: 1.0005x; 1.0005x over previous
#include <cuda_runtime.h>
#include <math.h>

#define HD    1024
#define KH    8
#define BATCH 8192
#define EPSLN 1e-5f

// ---------------- scratch (static device globals; no allocs allowed) --------
static __device__ float g_y1[(size_t)BATCH * 2 * HD];   //  64 MB : x@W1+b1 -> ln/relu in place
static __device__ float g_xe[(size_t)BATCH * HD];       //  32 MB : x@We1_top + be1
static __device__ float g_e [(size_t)BATCH * KH * HD];  // 256 MB : pre-LN evaluator activations

// ---------------- 128x128x16 fp32 GEMM, 256 thr, 8x8 per thread -------------
// C[M,N] = A[M,Kd] @ W[Kd,N] (+ bias[n]) (+ addv[row>>3][n] if ADD_BCAST)
template<bool ADD_BCAST>
__global__ void __launch_bounds__(256, 2) sgemm128(
    const float* __restrict__ A, const float* __restrict__ Wm,
    const float* __restrict__ bias, const float* __restrict__ addv,
    float* __restrict__ C, int M, int N, int Kd)
{
    __shared__ float As[16][128];   // A tile, transposed (k-major)
    __shared__ float Bs[16][128];

    const int bn  = blockIdx.x * 128;
    const int bm  = blockIdx.y * 128;
    const int tid = threadIdx.x;
    const int tx  = tid & 15;       // 16 cols of threads
    const int ty  = tid >> 4;       // 16 rows of threads

    float acc[8][8];
    #pragma unroll
    for (int i = 0; i < 8; i++)
        #pragma unroll
        for (int j = 0; j < 8; j++) acc[i][j] = 0.f;

    const float* Aptr = A  + (size_t)bm * Kd;
    const float* Bptr = Wm + bn;

    const int arow = tid >> 2;          // 0..63 (two passes -> 128 rows)
    const int acol = (tid & 3) * 4;     // 0,4,8,12
    const int brow = tid >> 5;          // 0..7 (two passes -> 16 rows)
    const int bcol = (tid & 31) * 4;    // 0..124

    for (int k0 = 0; k0 < Kd; k0 += 16) {
        #pragma unroll
        for (int i = 0; i < 2; i++) {
            int r = arow + i * 64;
            float4 v = *(const float4*)(Aptr + (size_t)r * Kd + k0 + acol);
            As[acol + 0][r] = v.x;
            As[acol + 1][r] = v.y;
            As[acol + 2][r] = v.z;
            As[acol + 3][r] = v.w;
        }
        #pragma unroll
        for (int i = 0; i < 2; i++) {
            int r = brow + i * 8;
            float4 v = *(const float4*)(Bptr + (size_t)(k0 + r) * N + bcol);
            *(float4*)&Bs[r][bcol] = v;
        }
        __syncthreads();

        #pragma unroll
        for (int kk = 0; kk < 16; kk++) {
            float ra[8], rb[8];
            *(float4*)&ra[0] = *(const float4*)&As[kk][ty * 4];
            *(float4*)&ra[4] = *(const float4*)&As[kk][64 + ty * 4];
            *(float4*)&rb[0] = *(const float4*)&Bs[kk][tx * 4];
            *(float4*)&rb[4] = *(const float4*)&Bs[kk][64 + tx * 4];
            #pragma unroll
            for (int i = 0; i < 8; i++)
                #pragma unroll
                for (int j = 0; j < 8; j++)
                    acc[i][j] = fmaf(ra[i], rb[j], acc[i][j]);
        }
        __syncthreads();
    }

    // epilogue: two 4-row quads x two 4-col quads
    #pragma unroll
    for (int iq = 0; iq < 2; iq++) {
        #pragma unroll
        for (int ii = 0; ii < 4; ii++) {
            int rm = bm + iq * 64 + ty * 4 + ii;
            float* crow = C + (size_t)rm * N;
            const float* arow2 = ADD_BCAST ? (addv + (size_t)(rm >> 3) * N) : nullptr;
            #pragma unroll
            for (int jq = 0; jq < 2; jq++) {
                int cn = bn + jq * 64 + tx * 4;
                float4 v;
                float o0 = acc[iq * 4 + ii][jq * 4 + 0];
                float o1 = acc[iq * 4 + ii][jq * 4 + 1];
                float o2 = acc[iq * 4 + ii][jq * 4 + 2];
                float o3 = acc[iq * 4 + ii][jq * 4 + 3];
                if (bias) {
                    o0 += bias[cn + 0]; o1 += bias[cn + 1];
                    o2 += bias[cn + 2]; o3 += bias[cn + 3];
                }
                if (ADD_BCAST) {
                    o0 += arow2[cn + 0]; o1 += arow2[cn + 1];
                    o2 += arow2[cn + 2]; o3 += arow2[cn + 3];
                }
                v.x = o0; v.y = o1; v.z = o2; v.w = o3;
                *(float4*)(crow + cn) = v;
            }
        }
    }
}

// ---------------- block reduction of two scalars (256 threads) --------------
__device__ __forceinline__ void block_reduce2(float& a, float& b) {
    __shared__ float sa[8], sb[8];
    float x = a, y = b;
    #pragma unroll
    for (int o = 16; o > 0; o >>= 1) {
        x += __shfl_down_sync(0xffffffffu, x, o);
        y += __shfl_down_sync(0xffffffffu, y, o);
    }
    int w = threadIdx.x >> 5;
    if ((threadIdx.x & 31) == 0) { sa[w] = x; sb[w] = y; }
    __syncthreads();
    if (threadIdx.x == 0) {
        float xs = 0.f, ys = 0.f;
        #pragma unroll
        for (int i = 0; i < 8; i++) { xs += sa[i]; ys += sb[i]; }
        sa[0] = xs; sb[0] = ys;
    }
    __syncthreads();
    a = sa[0]; b = sb[0];
    __syncthreads();
}

// ---------------- LN + ReLU in place over width 2048 ------------------------
__global__ void __launch_bounds__(256) ln_relu_2048(
    float* __restrict__ y, const float* __restrict__ g, const float* __restrict__ beta)
{
    const int row = blockIdx.x;
    float* p = y + (size_t)row * 2048;
    const int t = threadIdx.x;
    float v[8];
    float s = 0.f, ss = 0.f;
    #pragma unroll
    for (int i = 0; i < 8; i++) {
        v[i] = p[t + i * 256];
        s += v[i]; ss += v[i] * v[i];
    }
    block_reduce2(s, ss);
    const float mean = s * (1.f / 2048.f);
    const float var  = ss * (1.f / 2048.f) - mean * mean;
    const float rs   = rsqrtf(var + EPSLN);
    #pragma unroll
    for (int i = 0; i < 8; i++) {
        int j = t + i * 256;
        float o = (v[i] - mean) * rs * g[j] + beta[j];
        p[j] = fmaxf(o, 0.f);
    }
}

// ---------------- per-(b,k) row: LN + ReLU + dot(We2) + sigmoid -------------
__global__ void __launch_bounds__(256) score_kernel(
    const float* __restrict__ e, const float* __restrict__ ge,
    const float* __restrict__ betae, const float* __restrict__ We2,
    const float* __restrict__ be2, float* __restrict__ scores)
{
    const int row = blockIdx.x;             // 0 .. B*K-1
    const float* p = e + (size_t)row * HD;
    const int t = threadIdx.x;
    float v[4];
    float s = 0.f, ss = 0.f;
    #pragma unroll
    for (int i = 0; i < 4; i++) {
        v[i] = p[t + i * 256];
        s += v[i]; ss += v[i] * v[i];
    }
    block_reduce2(s, ss);
    const float mean = s * (1.f / 1024.f);
    const float var  = ss * (1.f / 1024.f) - mean * mean;
    const float rs   = rsqrtf(var + EPSLN);
    float d = 0.f, dummy = 0.f;
    #pragma unroll
    for (int i = 0; i < 4; i++) {
        int j = t + i * 256;
        float o = fmaxf((v[i] - mean) * rs * ge[j] + betae[j], 0.f);
        d = fmaf(o, We2[j], d);
    }
    block_reduce2(d, dummy);
    if (t == 0) scores[row] = 1.f / (1.f + expf(-(d + be2[0])));
}

// ---------------- argmax over K, gather best hypothesis ---------------------
__global__ void __launch_bounds__(128) finalize_kernel(
    const float* __restrict__ scores, const float* __restrict__ hyps,
    float* __restrict__ best_hyp, float* __restrict__ best_idx,
    float* __restrict__ best_sc)
{
    const int b = blockIdx.x;
    __shared__ int sidx;
    if (threadIdx.x == 0) {
        const float* sc = scores + (size_t)b * KH;
        int bi = 0; float bv = sc[0];
        #pragma unroll
        for (int k = 1; k < KH; k++)
            if (sc[k] > bv) { bv = sc[k]; bi = k; }   // strict > keeps first max (jnp.argmax)
        sidx = bi;
        best_idx[b] = (float)bi;
        best_sc[b]  = bv;
    }
    __syncthreads();
    const float* src = hyps + ((size_t)b * KH + sidx) * HD;
    float* dst = best_hyp + (size_t)b * HD;
    #pragma unroll
    for (int i = 0; i < HD / 128; i++)
        dst[threadIdx.x + i * 128] = src[threadIdx.x + i * 128];
}

// ---------------- launcher ---------------------------------------------------
extern "C" void kernel_launch(void* const* d_in, const int* in_sizes, int n_in,
                              void* d_out, int out_size)
{
    const float* x     = (const float*)d_in[0];
    const float* W1    = (const float*)d_in[1];
    const float* b1    = (const float*)d_in[2];
    const float* g1    = (const float*)d_in[3];
    const float* beta1 = (const float*)d_in[4];
    const float* W2    = (const float*)d_in[5];
    const float* b2    = (const float*)d_in[6];
    const float* We1   = (const float*)d_in[7];
    const float* be1   = (const float*)d_in[8];
    const float* ge    = (const float*)d_in[9];
    const float* betae = (const float*)d_in[10];
    const float* We2   = (const float*)d_in[11];
    const float* be2   = (const float*)d_in[12];

    float* out = (float*)d_out;
    float* out_best_hyp = out;                                        // [B, H]
    float* out_hyps     = out + (size_t)BATCH * HD;                   // [B, K, H]
    float* out_scores   = out_hyps + (size_t)BATCH * KH * HD;         // [B, K]
    float* out_best_idx = out_scores + (size_t)BATCH * KH;            // [B, 1]
    float* out_best_sc  = out_best_idx + BATCH;                       // [B, 1]

    float *y1, *xe, *e;
    cudaGetSymbolAddress((void**)&y1, g_y1);
    cudaGetSymbolAddress((void**)&xe, g_xe);
    cudaGetSymbolAddress((void**)&e,  g_e);

    // G1: y1 = x @ W1 + b1                         [8192, 2048]
    sgemm128<false><<<dim3(2 * HD / 128, BATCH / 128), 256>>>(
        x, W1, b1, nullptr, y1, BATCH, 2 * HD, HD);

    // GX: xe = x @ We1[0:H,:] + be1                [8192, 1024]  (shared across K)
    sgemm128<false><<<dim3(HD / 128, BATCH / 128), 256>>>(
        x, We1, be1, nullptr, xe, BATCH, HD, HD);

    // LN + ReLU over width 2048, in place
    ln_relu_2048<<<BATCH, 256>>>(y1, g1, beta1);

    // G2: hyps = h @ W2 + b2                       [8192, 8192] -> d_out hyps region
    sgemm128<false><<<dim3(KH * HD / 128, BATCH / 128), 256>>>(
        y1, W2, b2, nullptr, out_hyps, BATCH, KH * HD, 2 * HD);

    // G3: e = hyps(view [B*K, H]) @ We1[H:2H,:] + xe[b]   [65536, 1024]
    sgemm128<true><<<dim3(HD / 128, BATCH * KH / 128), 256>>>(
        out_hyps, We1 + (size_t)HD * HD, nullptr, xe, e, BATCH * KH, HD, HD);

    // scores = sigmoid(relu(LN(e)) . We2 + be2)    [B, K]
    score_kernel<<<BATCH * KH, 256>>>(e, ge, betae, We2, be2, out_scores);

    // argmax / gather
    finalize_kernel<<<BATCH, 128>>>(out_scores, out_hyps,
                                    out_best_hyp, out_best_idx, out_best_sc);
}

// round 4
// speedup vs baseline: 1.1132x; 1.1127x over previous
#include <cuda_runtime.h>
#include <math.h>
#include <stdint.h>

#define HD    1024
#define KH    8
#define BATCH 8192
#define EPSLN 1e-5f

// ---------------- scratch (static device globals; no allocs allowed) --------
static __device__ float g_y1 [(size_t)BATCH * 2 * HD];      //  64 MB
static __device__ float g_xe [(size_t)BATCH * HD];          //  32 MB
static __device__ float g_e  [(size_t)BATCH * KH * HD];     // 256 MB
static __device__ float g_w1t [(size_t)2 * HD * HD];        //   8 MB [2048,1024]
static __device__ float g_w2t [(size_t)KH * HD * 2 * HD];   //  64 MB [8192,2048]
static __device__ float g_we1t[(size_t)HD * 2 * HD];        //   8 MB [1024,2048]

// ============================ PTX helpers (portable, sm_80+) =================
__device__ __forceinline__ uint32_t smem_u32(const void* p) {
    uint32_t a;
    asm("{ .reg .u64 t; cvta.to.shared.u64 t, %1; cvt.u32.u64 %0, t; }" : "=r"(a) : "l"(p));
    return a;
}
__device__ __forceinline__ void cp_async16(uint32_t saddr, const void* g) {
    asm volatile("cp.async.cg.shared.global [%0], [%1], 16;" :: "r"(saddr), "l"(g));
}
__device__ __forceinline__ void cp_commit() {
    asm volatile("cp.async.commit_group;" ::: "memory");
}
template<int N> __device__ __forceinline__ void cp_wait() {
    asm volatile("cp.async.wait_group %0;" :: "n"(N) : "memory");
}
__device__ __forceinline__ uint32_t f2tf32(float f) {
    uint32_t r;
    asm("cvt.rna.tf32.f32 %0, %1;" : "=r"(r) : "f"(f));
    return r;
}
__device__ __forceinline__ void mma8(float* c, const uint32_t* a, const uint32_t* b) {
    asm volatile(
        "mma.sync.aligned.m16n8k8.row.col.f32.tf32.tf32.f32 "
        "{%0,%1,%2,%3}, {%4,%5,%6,%7}, {%8,%9}, {%0,%1,%2,%3};"
        : "+f"(c[0]), "+f"(c[1]), "+f"(c[2]), "+f"(c[3])
        : "r"(a[0]), "r"(a[1]), "r"(a[2]), "r"(a[3]), "r"(b[0]), "r"(b[1]));
}

// ============================ tf32x3 GEMM (mma.sync) =========================
// C[M,N] = A[M,Kd] @ Bt[N,Kd]^T  (+ bias[n])  (+ aux[(row>>3)*N + n] if BCAST)
// CTA tile 128x128, 8 warps (4 m x 2 n), warp tile 32x64 (2x8 m16n8k8 tiles).
// 3-stage cp.async pipeline, BK=16 per stage. SMEM rows padded to 20 floats
// (80 B, 16B-aligned for cp.async, conflict-free fragment loads).
#define BM 128
#define BN 128
#define BKS 16
#define STAGES 3
#define PITCH 20                               // floats per k-row (16 + 4 pad)
#define TILE_FLOATS (128 * PITCH)              // 2560 floats = 10 KB
#define STAGE_FLOATS (2 * TILE_FLOATS)         // A tile + B tile
#define SMEM_DYN (STAGES * STAGE_FLOATS * 4)   // 61440 B

template<bool BCAST>
__global__ void __launch_bounds__(256, 1) mma_gemm(
    const float* __restrict__ A, int lda,
    const float* __restrict__ B, int ldb,      // B is [N,Kd] K-major (pre-transposed)
    const float* __restrict__ aux,             // bias[N] or addv[M/8, N]
    float* __restrict__ C, int N, int Kd)
{
    extern __shared__ float smem[];
    const uint32_t sbase = smem_u32(smem);
    const int tid  = threadIdx.x;
    const int bm   = blockIdx.x * BM;
    const int bn   = blockIdx.y * BN;
    const int lane = tid & 31;
    const int wid  = tid >> 5;
    const int wm   = wid & 3;                  // 4 warp-rows of 32
    const int wn   = wid >> 2;                 // 2 warp-cols of 64
    const int g    = lane >> 2;                // group id 0..7
    const int tg   = lane & 3;                 // thread-in-group 0..3

    float acc[2][8][4];
    #pragma unroll
    for (int mt = 0; mt < 2; mt++)
        #pragma unroll
        for (int nt = 0; nt < 8; nt++)
            #pragma unroll
            for (int i = 0; i < 4; i++) acc[mt][nt][i] = 0.f;

    // per-stage loader: 512 16B chunks for A, 512 for B; 2+2 per thread
    const int lrow = tid >> 2;                 // 0..63
    const int lkc  = tid & 3;                  // chunk col 0..3 (k = lkc*4..lkc*4+3)
    auto load_stage = [&](int it, int s) {
        const uint32_t st = sbase + s * (STAGE_FLOATS * 4);
        const int k0 = it * BKS;
        #pragma unroll
        for (int h = 0; h < 2; h++) {
            int m = lrow + h * 64;
            cp_async16(st + (m * PITCH + lkc * 4) * 4,
                       A + (size_t)(bm + m) * lda + k0 + lkc * 4);
        }
        #pragma unroll
        for (int h = 0; h < 2; h++) {
            int n = lrow + h * 64;
            cp_async16(st + (TILE_FLOATS + n * PITCH + lkc * 4) * 4,
                       B + (size_t)(bn + n) * ldb + k0 + lkc * 4);
        }
    };

    const int nstage = Kd / BKS;
    #pragma unroll
    for (int s = 0; s < STAGES - 1; s++) { load_stage(s, s); cp_commit(); }

    for (int it = 0; it < nstage; it++) {
        cp_wait<STAGES - 2>();
        __syncthreads();
        {   // prefetch (overwrites buffer of iter it-1; safe after the sync)
            int nb = it + STAGES - 1;
            if (nb < nstage) load_stage(nb, nb % STAGES);
            cp_commit();
        }
        const float* buf = smem + (it % STAGES) * STAGE_FLOATS;
        const float* sA = buf;
        const float* sB = buf + TILE_FLOATS;

        #pragma unroll
        for (int ks = 0; ks < 2; ks++) {
            const int kk = ks * 8;
            uint32_t aH[2][4], aL[2][4], bH[8][2], bL[8][2];
            #pragma unroll
            for (int mt = 0; mt < 2; mt++) {
                const int r0 = wm * 32 + mt * 16 + g;
                #pragma unroll
                for (int i = 0; i < 4; i++) {
                    int rr = r0 + (i & 1) * 8;
                    int cc = kk + tg + (i >> 1) * 4;
                    float f = sA[rr * PITCH + cc];
                    uint32_t h = f2tf32(f);
                    aH[mt][i] = h;
                    aL[mt][i] = f2tf32(f - __uint_as_float(h));
                }
            }
            #pragma unroll
            for (int nt = 0; nt < 8; nt++) {
                const int n = wn * 64 + nt * 8 + g;
                #pragma unroll
                for (int i = 0; i < 2; i++) {
                    float f = sB[n * PITCH + kk + tg + i * 4];
                    uint32_t h = f2tf32(f);
                    bH[nt][i] = h;
                    bL[nt][i] = f2tf32(f - __uint_as_float(h));
                }
            }
            #pragma unroll
            for (int mt = 0; mt < 2; mt++)
                #pragma unroll
                for (int nt = 0; nt < 8; nt++) {
                    mma8(acc[mt][nt], aH[mt], bL[nt]);
                    mma8(acc[mt][nt], aL[mt], bH[nt]);
                    mma8(acc[mt][nt], aH[mt], bH[nt]);
                }
        }
        // no trailing sync needed: next iteration's top sync orders reuse
    }

    // ---------------- epilogue --------------------------------------------
    #pragma unroll
    for (int mt = 0; mt < 2; mt++) {
        const int row0 = bm + wm * 32 + mt * 16 + g;
        #pragma unroll
        for (int nt = 0; nt < 8; nt++) {
            const int col = bn + wn * 64 + nt * 8 + 2 * tg;
            float o0 = acc[mt][nt][0], o1 = acc[mt][nt][1];
            float o2 = acc[mt][nt][2], o3 = acc[mt][nt][3];
            if (!BCAST) {
                float z0 = aux[col], z1 = aux[col + 1];
                o0 += z0; o1 += z1; o2 += z0; o3 += z1;
            } else {
                const float* a0 = aux + (size_t)(row0 >> 3) * N + col;
                const float* a1 = aux + (size_t)((row0 + 8) >> 3) * N + col;
                o0 += a0[0]; o1 += a0[1]; o2 += a1[0]; o3 += a1[1];
            }
            *(float2*)(C + (size_t)row0 * N + col)       = make_float2(o0, o1);
            *(float2*)(C + (size_t)(row0 + 8) * N + col) = make_float2(o2, o3);
        }
    }
}

// ============================ transpose [R,C] -> [C,R] =======================
__global__ void __launch_bounds__(256) transpose_k(
    const float* __restrict__ in, float* __restrict__ out, int R, int C)
{
    __shared__ float t[32][33];
    const int bx = blockIdx.x * 32;
    const int by = blockIdx.y * 32;
    {
        int x = bx + threadIdx.x;
        #pragma unroll
        for (int j = 0; j < 32; j += 8) {
            int y = by + threadIdx.y + j;
            t[threadIdx.y + j][threadIdx.x] = in[(size_t)y * C + x];
        }
    }
    __syncthreads();
    {
        int x = by + threadIdx.x;
        #pragma unroll
        for (int j = 0; j < 32; j += 8) {
            int y = bx + threadIdx.y + j;
            out[(size_t)y * R + x] = t[threadIdx.x][threadIdx.y + j];
        }
    }
}

// ---------------- block reduction of two scalars (256 threads) --------------
__device__ __forceinline__ void block_reduce2(float& a, float& b) {
    __shared__ float sa[8], sb[8];
    float x = a, y = b;
    #pragma unroll
    for (int o = 16; o > 0; o >>= 1) {
        x += __shfl_down_sync(0xffffffffu, x, o);
        y += __shfl_down_sync(0xffffffffu, y, o);
    }
    int w = threadIdx.x >> 5;
    if ((threadIdx.x & 31) == 0) { sa[w] = x; sb[w] = y; }
    __syncthreads();
    if (threadIdx.x == 0) {
        float xs = 0.f, ys = 0.f;
        #pragma unroll
        for (int i = 0; i < 8; i++) { xs += sa[i]; ys += sb[i]; }
        sa[0] = xs; sb[0] = ys;
    }
    __syncthreads();
    a = sa[0]; b = sb[0];
    __syncthreads();
}

// ---------------- LN + ReLU in place over width 2048 ------------------------
__global__ void __launch_bounds__(256) ln_relu_2048(
    float* __restrict__ y, const float* __restrict__ g, const float* __restrict__ beta)
{
    const int row = blockIdx.x;
    float* p = y + (size_t)row * 2048;
    const int t = threadIdx.x;
    float v[8];
    float s = 0.f, ss = 0.f;
    #pragma unroll
    for (int i = 0; i < 8; i++) {
        v[i] = p[t + i * 256];
        s += v[i]; ss += v[i] * v[i];
    }
    block_reduce2(s, ss);
    const float mean = s * (1.f / 2048.f);
    const float var  = ss * (1.f / 2048.f) - mean * mean;
    const float rs   = rsqrtf(var + EPSLN);
    #pragma unroll
    for (int i = 0; i < 8; i++) {
        int j = t + i * 256;
        float o = (v[i] - mean) * rs * g[j] + beta[j];
        p[j] = fmaxf(o, 0.f);
    }
}

// ---------------- per-(b,k) row: LN + ReLU + dot(We2) + sigmoid -------------
__global__ void __launch_bounds__(256) score_kernel(
    const float* __restrict__ e, const float* __restrict__ ge,
    const float* __restrict__ betae, const float* __restrict__ We2,
    const float* __restrict__ be2, float* __restrict__ scores)
{
    const int row = blockIdx.x;
    const float* p = e + (size_t)row * HD;
    const int t = threadIdx.x;
    float v[4];
    float s = 0.f, ss = 0.f;
    #pragma unroll
    for (int i = 0; i < 4; i++) {
        v[i] = p[t + i * 256];
        s += v[i]; ss += v[i] * v[i];
    }
    block_reduce2(s, ss);
    const float mean = s * (1.f / 1024.f);
    const float var  = ss * (1.f / 1024.f) - mean * mean;
    const float rs   = rsqrtf(var + EPSLN);
    float d = 0.f, dummy = 0.f;
    #pragma unroll
    for (int i = 0; i < 4; i++) {
        int j = t + i * 256;
        float o = fmaxf((v[i] - mean) * rs * ge[j] + betae[j], 0.f);
        d = fmaf(o, We2[j], d);
    }
    block_reduce2(d, dummy);
    if (t == 0) scores[row] = 1.f / (1.f + expf(-(d + be2[0])));
}

// ---------------- argmax over K, gather best hypothesis ---------------------
__global__ void __launch_bounds__(128) finalize_kernel(
    const float* __restrict__ scores, const float* __restrict__ hyps,
    float* __restrict__ best_hyp, float* __restrict__ best_idx,
    float* __restrict__ best_sc)
{
    const int b = blockIdx.x;
    __shared__ int sidx;
    if (threadIdx.x == 0) {
        const float* sc = scores + (size_t)b * KH;
        int bi = 0; float bv = sc[0];
        #pragma unroll
        for (int k = 1; k < KH; k++)
            if (sc[k] > bv) { bv = sc[k]; bi = k; }
        sidx = bi;
        best_idx[b] = (float)bi;
        best_sc[b]  = bv;
    }
    __syncthreads();
    const float* src = hyps + ((size_t)b * KH + sidx) * HD;
    float* dst = best_hyp + (size_t)b * HD;
    #pragma unroll
    for (int i = 0; i < HD / 128; i++)
        dst[threadIdx.x + i * 128] = src[threadIdx.x + i * 128];
}

// ---------------- launcher ---------------------------------------------------
extern "C" void kernel_launch(void* const* d_in, const int* in_sizes, int n_in,
                              void* d_out, int out_size)
{
    const float* x     = (const float*)d_in[0];
    const float* W1    = (const float*)d_in[1];
    const float* b1    = (const float*)d_in[2];
    const float* g1    = (const float*)d_in[3];
    const float* beta1 = (const float*)d_in[4];
    const float* W2    = (const float*)d_in[5];
    const float* b2    = (const float*)d_in[6];
    const float* We1   = (const float*)d_in[7];
    const float* be1   = (const float*)d_in[8];
    const float* ge    = (const float*)d_in[9];
    const float* betae = (const float*)d_in[10];
    const float* We2   = (const float*)d_in[11];
    const float* be2   = (const float*)d_in[12];

    float* out = (float*)d_out;
    float* out_best_hyp = out;                                    // [B, H]
    float* out_hyps     = out + (size_t)BATCH * HD;               // [B, K, H]
    float* out_scores   = out_hyps + (size_t)BATCH * KH * HD;     // [B, K]
    float* out_best_idx = out_scores + (size_t)BATCH * KH;        // [B, 1]
    float* out_best_sc  = out_best_idx + BATCH;                   // [B, 1]

    float *y1, *xe, *e, *w1t, *w2t, *we1t;
    cudaGetSymbolAddress((void**)&y1,   g_y1);
    cudaGetSymbolAddress((void**)&xe,   g_xe);
    cudaGetSymbolAddress((void**)&e,    g_e);
    cudaGetSymbolAddress((void**)&w1t,  g_w1t);
    cudaGetSymbolAddress((void**)&w2t,  g_w2t);
    cudaGetSymbolAddress((void**)&we1t, g_we1t);

    cudaFuncSetAttribute(mma_gemm<false>, cudaFuncAttributeMaxDynamicSharedMemorySize, SMEM_DYN);
    cudaFuncSetAttribute(mma_gemm<true>,  cudaFuncAttributeMaxDynamicSharedMemorySize, SMEM_DYN);

    // transpose weights to [N, K] K-major
    transpose_k<<<dim3(2 * HD / 32, HD / 32),      dim3(32, 8)>>>(W1,  w1t,  HD,     2 * HD);
    transpose_k<<<dim3(KH * HD / 32, 2 * HD / 32), dim3(32, 8)>>>(W2,  w2t,  2 * HD, KH * HD);
    transpose_k<<<dim3(HD / 32, 2 * HD / 32),      dim3(32, 8)>>>(We1, we1t, 2 * HD, HD);

    // G1: y1 = x @ W1 + b1                       [8192, 2048], K=1024
    mma_gemm<false><<<dim3(BATCH / BM, 2 * HD / BN), 256, SMEM_DYN>>>(
        x, HD, w1t, HD, b1, y1, 2 * HD, HD);

    // GX: xe = x @ We1[0:H,:] + be1              [8192, 1024], K=1024
    mma_gemm<false><<<dim3(BATCH / BM, HD / BN), 256, SMEM_DYN>>>(
        x, HD, we1t, 2 * HD, be1, xe, HD, HD);

    // LN + ReLU width 2048, in place
    ln_relu_2048<<<BATCH, 256>>>(y1, g1, beta1);

    // G2: hyps = h @ W2 + b2                     [8192, 8192], K=2048
    mma_gemm<false><<<dim3(BATCH / BM, KH * HD / BN), 256, SMEM_DYN>>>(
        y1, 2 * HD, w2t, 2 * HD, b2, out_hyps, KH * HD, 2 * HD);

    // G3: e = hyps @ We1[H:2H,:] + xe[row>>3]    [65536, 1024], K=1024
    mma_gemm<true><<<dim3(BATCH * KH / BM, HD / BN), 256, SMEM_DYN>>>(
        out_hyps, HD, we1t + HD, 2 * HD, xe, e, HD, HD);

    // scores = sigmoid(relu(LN(e)) . We2 + be2)
    score_kernel<<<BATCH * KH, 256>>>(e, ge, betae, We2, be2, out_scores);

    // argmax / gather
    finalize_kernel<<<BATCH, 128>>>(out_scores, out_hyps,
                                    out_best_hyp, out_best_idx, out_best_sc);
}

// round 5
// speedup vs baseline: 1.1524x; 1.0352x over previous
#include <cuda_runtime.h>
#include <math.h>
#include <stdint.h>

#define HD    1024
#define KH    8
#define BATCH 8192
#define EPSLN 1e-5f

// ---------------- scratch (static device globals; no allocs allowed) --------
static __device__ float  g_y1 [(size_t)BATCH * 2 * HD];          //  64 MB plain G1 out
static __device__ float  g_xe [(size_t)BATCH * HD];              //  32 MB plain GX out
static __device__ float  g_e  [(size_t)BATCH * KH * HD];         // 256 MB plain G3 out (permuted rows)
static __device__ float2 g_xs [(size_t)BATCH * HD];              //  64 MB x split tiles
static __device__ float2 g_hs [(size_t)BATCH * 2 * HD];          // 128 MB h split tiles
static __device__ float2 g_as [(size_t)BATCH * KH * HD];         // 512 MB hyps-as-G3A split tiles
static __device__ float2 g_w1s [(size_t)2 * HD * HD];            //  16 MB W1^T split tiles
static __device__ float2 g_w2s [(size_t)KH * HD * 2 * HD];       // 128 MB W2^T split tiles
static __device__ float2 g_we1s[(size_t)HD * 2 * HD];            //  16 MB We1^T split tiles

// ============================ PTX helpers (portable, sm_80+) =================
__device__ __forceinline__ uint32_t smem_u32(const void* p) {
    uint32_t a;
    asm("{ .reg .u64 t; cvta.to.shared.u64 t, %1; cvt.u32.u64 %0, t; }" : "=r"(a) : "l"(p));
    return a;
}
__device__ __forceinline__ void cp_async16(uint32_t saddr, const void* g) {
    asm volatile("cp.async.cg.shared.global [%0], [%1], 16;" :: "r"(saddr), "l"(g));
}
__device__ __forceinline__ void cp_commit() {
    asm volatile("cp.async.commit_group;" ::: "memory");
}
template<int N> __device__ __forceinline__ void cp_wait() {
    asm volatile("cp.async.wait_group %0;" :: "n"(N) : "memory");
}
__device__ __forceinline__ uint32_t f2tf32(float f) {
    uint32_t r;
    asm("cvt.rna.tf32.f32 %0, %1;" : "=r"(r) : "f"(f));
    return r;
}
__device__ __forceinline__ float2 split2(float v) {
    float hi = __uint_as_float(f2tf32(v));
    return make_float2(hi, __uint_as_float(f2tf32(v - hi)));
}
__device__ __forceinline__ void mma8(float* c, const uint32_t* a, const uint32_t* b) {
    asm volatile(
        "mma.sync.aligned.m16n8k8.row.col.f32.tf32.tf32.f32 "
        "{%0,%1,%2,%3}, {%4,%5,%6,%7}, {%8,%9}, {%0,%1,%2,%3};"
        : "+f"(c[0]), "+f"(c[1]), "+f"(c[2]), "+f"(c[3])
        : "r"(a[0]), "r"(a[1]), "r"(a[2]), "r"(a[3]), "r"(b[0]), "r"(b[1]));
}

// Split-tile format (both A and B operands):
//   tile = one (128 rows x 32 k) block = 2048 float4 = 32 KB.
//   float4 index within tile: (kb*128 + row)*4 + tg, kb = k8-block (0..3),
//   tg = k&3; float4 = {hi(k=kb*8+tg), lo, hi(k=kb*8+tg+4), lo}.
//   Element (row, k): kb=(k>>3)&3, tg=k&3, half=(k>>2)&1 -> float2 slot idx4*2+half.
#define TF4 2048

__device__ __forceinline__ void split_store(float2* base, size_t tile, int row, int k, float v) {
    int idx4 = ((((k >> 3) & 3) * 128 + row) << 2) + (k & 3);
    base[tile * (TF4 * 2) + idx4 * 2 + ((k >> 2) & 1)] = split2(v);
}

// ============================ tf32x3 GEMM (pre-split tiles) ==================
// C[M,N] = A @ B^T from pre-split tiles. 128x128 CTA, 8 warps 4x2, BK=32.
// MODE 0: +bias[n].  MODE 1: +bias, also writes G3-A split tiles (G2).
// MODE 2: +aux[(row & 8191)*N + n]  (G3 row-permuted broadcast add).
#define SMEM_DYN (3 * 64 * 1024)

template<int MODE>
__global__ void __launch_bounds__(256, 1) mma_gemm(
    const float4* __restrict__ At, int nAk,
    const float4* __restrict__ Bt, int nBk, int koff, int nk,
    const float* __restrict__ aux, float* __restrict__ C, int N,
    float2* __restrict__ sp)
{
    extern __shared__ float4 sm4[];          // 3 bufs x 4096 float4 (A 2048 | B 2048)
    const int tid  = threadIdx.x;
    const int lane = tid & 31, wid = tid >> 5;
    const int wm = wid & 3, wn = wid >> 2;
    const int g = lane >> 2, tg = lane & 3;
    const int bm = blockIdx.x * 128, bn = blockIdx.y * 128;

    float acc[2][8][4];
    #pragma unroll
    for (int mt = 0; mt < 2; mt++)
        #pragma unroll
        for (int nt = 0; nt < 8; nt++)
            #pragma unroll
            for (int i = 0; i < 4; i++) acc[mt][nt][i] = 0.f;

    const float4* Ab = At + (size_t)blockIdx.x * nAk * TF4 + tid;
    const float4* Bb = Bt + ((size_t)blockIdx.y * nBk + koff) * TF4 + tid;

    auto load_stage = [&](int s, int buf) {
        const float4* a = Ab + (size_t)s * TF4;
        const float4* b = Bb + (size_t)s * TF4;
        uint32_t d = smem_u32(&sm4[buf * 4096 + tid]);
        #pragma unroll
        for (int i = 0; i < 8; i++) cp_async16(d + i * 4096, a + i * 256);
        d += 2048 * 16;
        #pragma unroll
        for (int i = 0; i < 8; i++) cp_async16(d + i * 4096, b + i * 256);
    };

    load_stage(0, 0); cp_commit();
    load_stage(1, 1); cp_commit();

    for (int it = 0; it < nk; it++) {
        cp_wait<1>();
        __syncthreads();
        if (it + 2 < nk) load_stage(it + 2, (it + 2) % 3);
        cp_commit();

        const float4* sA = &sm4[(it % 3) * 4096];
        const float4* sB = sA + 2048;
        #pragma unroll
        for (int kb = 0; kb < 4; kb++) {
            uint32_t aH[2][4], aL[2][4], bH[8][2], bL[8][2];
            #pragma unroll
            for (int mt = 0; mt < 2; mt++) {
                const int rr = wm * 32 + mt * 16 + g;
                float4 v0 = sA[((kb * 128 + rr)     << 2) + tg];
                float4 v1 = sA[((kb * 128 + rr + 8) << 2) + tg];
                aH[mt][0] = __float_as_uint(v0.x); aH[mt][1] = __float_as_uint(v1.x);
                aH[mt][2] = __float_as_uint(v0.z); aH[mt][3] = __float_as_uint(v1.z);
                aL[mt][0] = __float_as_uint(v0.y); aL[mt][1] = __float_as_uint(v1.y);
                aL[mt][2] = __float_as_uint(v0.w); aL[mt][3] = __float_as_uint(v1.w);
            }
            #pragma unroll
            for (int nt = 0; nt < 8; nt++) {
                const int n = wn * 64 + nt * 8 + g;
                float4 w = sB[((kb * 128 + n) << 2) + tg];
                bH[nt][0] = __float_as_uint(w.x); bH[nt][1] = __float_as_uint(w.z);
                bL[nt][0] = __float_as_uint(w.y); bL[nt][1] = __float_as_uint(w.w);
            }
            #pragma unroll
            for (int nt = 0; nt < 8; nt++) { mma8(acc[0][nt], aH[0], bL[nt]); mma8(acc[1][nt], aH[1], bL[nt]); }
            #pragma unroll
            for (int nt = 0; nt < 8; nt++) { mma8(acc[0][nt], aL[0], bH[nt]); mma8(acc[1][nt], aL[1], bH[nt]); }
            #pragma unroll
            for (int nt = 0; nt < 8; nt++) { mma8(acc[0][nt], aH[0], bH[nt]); mma8(acc[1][nt], aH[1], bH[nt]); }
        }
    }

    // ---------------- epilogue --------------------------------------------
    #pragma unroll
    for (int mt = 0; mt < 2; mt++) {
        const int row0 = bm + wm * 32 + mt * 16 + g;
        #pragma unroll
        for (int nt = 0; nt < 8; nt++) {
            const int col = bn + wn * 64 + nt * 8 + 2 * tg;
            float o0 = acc[mt][nt][0], o1 = acc[mt][nt][1];
            float o2 = acc[mt][nt][2], o3 = acc[mt][nt][3];
            if (MODE != 2) {
                float z0 = aux[col], z1 = aux[col + 1];
                o0 += z0; o1 += z1; o2 += z0; o3 += z1;
            } else {
                const float* a0 = aux + (size_t)(row0 & (BATCH - 1)) * N + col;
                const float* a1 = aux + (size_t)((row0 + 8) & (BATCH - 1)) * N + col;
                o0 += a0[0]; o1 += a0[1]; o2 += a1[0]; o3 += a1[1];
            }
            *(float2*)(C + (size_t)row0 * N + col)       = make_float2(o0, o1);
            *(float2*)(C + (size_t)(row0 + 8) * N + col) = make_float2(o2, o3);
            if (MODE == 1) {
                // write hyps as G3-A split tiles, permuted row r = k*8192 + b
                #pragma unroll
                for (int q = 0; q < 4; q++) {
                    int b = row0 + (q >> 1) * 8;
                    int c = col + (q & 1);
                    float v = (q == 0) ? o0 : (q == 1) ? o1 : (q == 2) ? o2 : o3;
                    int kk = c >> 10, h = c & 1023;
                    int r = kk * BATCH + b;
                    split_store(sp, (size_t)(r >> 7) * 32 + (h >> 5), r & 127, h & 31, v);
                }
            }
        }
    }
}

// ================= one-time weight transpose+split+tile ======================
// W [K][N] row-major  ->  B-split tiles [nblk][kblk], nBk = K/32 tiles per nblk.
__global__ void __launch_bounds__(256) wsplit_kernel(
    const float* __restrict__ W, float2* __restrict__ out, int N)
{
    __shared__ float s[32 * 132];
    const int t = threadIdx.x;
    #pragma unroll
    for (int i = 0; i < 16; i++) {
        int e = t + i * 256;
        int kl = e >> 7, nl = e & 127;
        s[kl * 132 + nl] = W[(size_t)(blockIdx.y * 32 + kl) * N + blockIdx.x * 128 + nl];
    }
    __syncthreads();
    float2* ob = out + ((size_t)blockIdx.x * gridDim.y + blockIdx.y) * (TF4 * 2);
    #pragma unroll
    for (int i = 0; i < 16; i++) {
        int o = t + i * 256;                 // float2 slot within tile
        int idx4 = o >> 1, half = o & 1;
        int tg = idx4 & 3, nl = (idx4 >> 2) & 127, kb = idx4 >> 9;
        int kl = kb * 8 + half * 4 + tg;
        ob[o] = split2(s[kl * 132 + nl]);
    }
}

// ================= x -> A-split tiles ========================================
__global__ void __launch_bounds__(256) xsplit_kernel(
    const float* __restrict__ x, float2* __restrict__ out)
{
    const int m = blockIdx.x;
    const float* p = x + (size_t)m * HD;
    #pragma unroll
    for (int i = 0; i < 4; i++) {
        int j = threadIdx.x + i * 256;
        split_store(out, (size_t)(m >> 7) * 32 + (j >> 5), m & 127, j & 31, p[j]);
    }
}

// ---------------- block reduction of two scalars (256 threads) --------------
__device__ __forceinline__ void block_reduce2(float& a, float& b) {
    __shared__ float sa[8], sb[8];
    float x = a, y = b;
    #pragma unroll
    for (int o = 16; o > 0; o >>= 1) {
        x += __shfl_down_sync(0xffffffffu, x, o);
        y += __shfl_down_sync(0xffffffffu, y, o);
    }
    int w = threadIdx.x >> 5;
    if ((threadIdx.x & 31) == 0) { sa[w] = x; sb[w] = y; }
    __syncthreads();
    if (threadIdx.x == 0) {
        float xs = 0.f, ys = 0.f;
        #pragma unroll
        for (int i = 0; i < 8; i++) { xs += sa[i]; ys += sb[i]; }
        sa[0] = xs; sb[0] = ys;
    }
    __syncthreads();
    a = sa[0]; b = sb[0];
    __syncthreads();
}

// -------- LN + ReLU over width 2048, writes h as A-split tiles (nAk=64) -----
__global__ void __launch_bounds__(256) ln_relu_split(
    const float* __restrict__ y, const float* __restrict__ g,
    const float* __restrict__ beta, float2* __restrict__ hs)
{
    const int row = blockIdx.x;
    const float* p = y + (size_t)row * 2048;
    const int t = threadIdx.x;
    float v[8];
    float s = 0.f, ss = 0.f;
    #pragma unroll
    for (int i = 0; i < 8; i++) {
        v[i] = p[t + i * 256];
        s += v[i]; ss += v[i] * v[i];
    }
    block_reduce2(s, ss);
    const float mean = s * (1.f / 2048.f);
    const float var  = ss * (1.f / 2048.f) - mean * mean;
    const float rs   = rsqrtf(var + EPSLN);
    #pragma unroll
    for (int i = 0; i < 8; i++) {
        int j = t + i * 256;
        float o = fmaxf((v[i] - mean) * rs * g[j] + beta[j], 0.f);
        split_store(hs, (size_t)(row >> 7) * 64 + (j >> 5), row & 127, j & 31, o);
    }
}

// ---------------- per permuted row: LN + ReLU + dot(We2) + sigmoid ----------
__global__ void __launch_bounds__(256) score_kernel(
    const float* __restrict__ e, const float* __restrict__ ge,
    const float* __restrict__ betae, const float* __restrict__ We2,
    const float* __restrict__ be2, float* __restrict__ scores)
{
    const int r = blockIdx.x;               // r = k*8192 + b
    const float* p = e + (size_t)r * HD;
    const int t = threadIdx.x;
    float v[4];
    float s = 0.f, ss = 0.f;
    #pragma unroll
    for (int i = 0; i < 4; i++) {
        v[i] = p[t + i * 256];
        s += v[i]; ss += v[i] * v[i];
    }
    block_reduce2(s, ss);
    const float mean = s * (1.f / 1024.f);
    const float var  = ss * (1.f / 1024.f) - mean * mean;
    const float rs   = rsqrtf(var + EPSLN);
    float d = 0.f, dummy = 0.f;
    #pragma unroll
    for (int i = 0; i < 4; i++) {
        int j = t + i * 256;
        float o = fmaxf((v[i] - mean) * rs * ge[j] + betae[j], 0.f);
        d = fmaf(o, We2[j], d);
    }
    block_reduce2(d, dummy);
    if (t == 0) {
        int b = r & (BATCH - 1), k = r >> 13;
        scores[(size_t)b * KH + k] = 1.f / (1.f + expf(-(d + be2[0])));
    }
}

// ---------------- argmax over K, gather best hypothesis ---------------------
__global__ void __launch_bounds__(128) finalize_kernel(
    const float* __restrict__ scores, const float* __restrict__ hyps,
    float* __restrict__ best_hyp, float* __restrict__ best_idx,
    float* __restrict__ best_sc)
{
    const int b = blockIdx.x;
    __shared__ int sidx;
    if (threadIdx.x == 0) {
        const float* sc = scores + (size_t)b * KH;
        int bi = 0; float bv = sc[0];
        #pragma unroll
        for (int k = 1; k < KH; k++)
            if (sc[k] > bv) { bv = sc[k]; bi = k; }
        sidx = bi;
        best_idx[b] = (float)bi;
        best_sc[b]  = bv;
    }
    __syncthreads();
    const float* src = hyps + ((size_t)b * KH + sidx) * HD;
    float* dst = best_hyp + (size_t)b * HD;
    #pragma unroll
    for (int i = 0; i < HD / 128; i++)
        dst[threadIdx.x + i * 128] = src[threadIdx.x + i * 128];
}

// ---------------- launcher ---------------------------------------------------
extern "C" void kernel_launch(void* const* d_in, const int* in_sizes, int n_in,
                              void* d_out, int out_size)
{
    const float* x     = (const float*)d_in[0];
    const float* W1    = (const float*)d_in[1];
    const float* b1    = (const float*)d_in[2];
    const float* g1    = (const float*)d_in[3];
    const float* beta1 = (const float*)d_in[4];
    const float* W2    = (const float*)d_in[5];
    const float* b2    = (const float*)d_in[6];
    const float* We1   = (const float*)d_in[7];
    const float* be1   = (const float*)d_in[8];
    const float* ge    = (const float*)d_in[9];
    const float* betae = (const float*)d_in[10];
    const float* We2   = (const float*)d_in[11];
    const float* be2   = (const float*)d_in[12];

    float* out = (float*)d_out;
    float* out_best_hyp = out;                                    // [B, H]
    float* out_hyps     = out + (size_t)BATCH * HD;               // [B, K, H]
    float* out_scores   = out_hyps + (size_t)BATCH * KH * HD;     // [B, K]
    float* out_best_idx = out_scores + (size_t)BATCH * KH;        // [B, 1]
    float* out_best_sc  = out_best_idx + BATCH;                   // [B, 1]

    float *y1, *xe, *e;
    float2 *xs, *hs, *as, *w1s, *w2s, *we1s;
    cudaGetSymbolAddress((void**)&y1,   g_y1);
    cudaGetSymbolAddress((void**)&xe,   g_xe);
    cudaGetSymbolAddress((void**)&e,    g_e);
    cudaGetSymbolAddress((void**)&xs,   g_xs);
    cudaGetSymbolAddress((void**)&hs,   g_hs);
    cudaGetSymbolAddress((void**)&as,   g_as);
    cudaGetSymbolAddress((void**)&w1s,  g_w1s);
    cudaGetSymbolAddress((void**)&w2s,  g_w2s);
    cudaGetSymbolAddress((void**)&we1s, g_we1s);

    cudaFuncSetAttribute(mma_gemm<0>, cudaFuncAttributeMaxDynamicSharedMemorySize, SMEM_DYN);
    cudaFuncSetAttribute(mma_gemm<1>, cudaFuncAttributeMaxDynamicSharedMemorySize, SMEM_DYN);
    cudaFuncSetAttribute(mma_gemm<2>, cudaFuncAttributeMaxDynamicSharedMemorySize, SMEM_DYN);

    // weight split tiles: W [K][N] -> [nblk][kblk]
    wsplit_kernel<<<dim3(2 * HD / 128, HD / 32),      256>>>(W1,  w1s,  2 * HD);  // nBk=32
    wsplit_kernel<<<dim3(KH * HD / 128, 2 * HD / 32), 256>>>(W2,  w2s,  KH * HD); // nBk=64
    wsplit_kernel<<<dim3(HD / 128, 2 * HD / 32),      256>>>(We1, we1s, HD);      // nBk=64

    // x split tiles (nAk=32)
    xsplit_kernel<<<BATCH, 256>>>(x, xs);

    // G1: y1 = x @ W1 + b1                       [8192, 2048], K=1024
    mma_gemm<0><<<dim3(BATCH / 128, 2 * HD / 128), 256, SMEM_DYN>>>(
        (const float4*)xs, 32, (const float4*)w1s, 32, 0, 32, b1, y1, 2 * HD, nullptr);

    // GX: xe = x @ We1[0:H,:] + be1              [8192, 1024], K=1024
    mma_gemm<0><<<dim3(BATCH / 128, HD / 128), 256, SMEM_DYN>>>(
        (const float4*)xs, 32, (const float4*)we1s, 64, 0, 32, be1, xe, HD, nullptr);

    // LN + ReLU -> h split tiles (nAk=64)
    ln_relu_split<<<BATCH, 256>>>(y1, g1, beta1, hs);

    // G2: hyps = h @ W2 + b2                     [8192, 8192], K=2048 (+G3-A split out)
    mma_gemm<1><<<dim3(BATCH / 128, KH * HD / 128), 256, SMEM_DYN>>>(
        (const float4*)hs, 64, (const float4*)w2s, 64, 0, 64, b2, out_hyps, KH * HD, as);

    // G3: e[r] = hyps_perm @ We1[H:2H,:] + xe[b] [65536, 1024], K=1024
    mma_gemm<2><<<dim3(BATCH * KH / 128, HD / 128), 256, SMEM_DYN>>>(
        (const float4*)as, 32, (const float4*)we1s, 64, 32, 32, xe, e, HD, nullptr);

    // scores = sigmoid(relu(LN(e)) . We2 + be2)
    score_kernel<<<BATCH * KH, 256>>>(e, ge, betae, We2, be2, out_scores);

    // argmax / gather
    finalize_kernel<<<BATCH, 128>>>(out_scores, out_hyps,
                                    out_best_hyp, out_best_idx, out_best_sc);
}

// round 6
// speedup vs baseline: 1.2392x; 1.0753x over previous
#include <cuda_runtime.h>
#include <math.h>
#include <stdint.h>

#define HD    1024
#define KH    8
#define BATCH 8192
#define EPSLN 1e-5f

// ---------------- scratch (static device globals; no allocs allowed) --------
static __device__ float  g_y1 [(size_t)BATCH * 2 * HD];          //  64 MB plain G1 out
static __device__ float  g_xe [(size_t)BATCH * HD];              //  32 MB plain GX out
static __device__ float  g_e  [(size_t)BATCH * KH * HD];         // 256 MB plain G3 out (permuted rows)
static __device__ float2 g_xs [(size_t)BATCH * HD];              //  64 MB x split tiles
static __device__ float2 g_hs [(size_t)BATCH * 2 * HD];          // 128 MB h split tiles
static __device__ float2 g_as [(size_t)BATCH * KH * HD];         // 512 MB hyps-as-G3A split tiles
static __device__ float2 g_w1s [(size_t)2 * HD * HD];            //  16 MB W1^T split tiles
static __device__ float2 g_w2s [(size_t)KH * HD * 2 * HD];       // 128 MB W2^T split tiles
static __device__ float2 g_we1s[(size_t)HD * 2 * HD];            //  16 MB We1^T split tiles

// ============================ PTX helpers (portable, sm_80+) =================
__device__ __forceinline__ uint32_t smem_u32(const void* p) {
    uint32_t a;
    asm("{ .reg .u64 t; cvta.to.shared.u64 t, %1; cvt.u32.u64 %0, t; }" : "=r"(a) : "l"(p));
    return a;
}
__device__ __forceinline__ void cp_async16(uint32_t saddr, const void* g) {
    asm volatile("cp.async.cg.shared.global [%0], [%1], 16;" :: "r"(saddr), "l"(g));
}
__device__ __forceinline__ void cp_commit() {
    asm volatile("cp.async.commit_group;" ::: "memory");
}
template<int N> __device__ __forceinline__ void cp_wait() {
    asm volatile("cp.async.wait_group %0;" :: "n"(N) : "memory");
}
__device__ __forceinline__ uint32_t f2tf32(float f) {
    uint32_t r;
    asm("cvt.rna.tf32.f32 %0, %1;" : "=r"(r) : "f"(f));
    return r;
}
__device__ __forceinline__ float2 split2(float v) {
    float hi = __uint_as_float(f2tf32(v));
    return make_float2(hi, __uint_as_float(f2tf32(v - hi)));
}
__device__ __forceinline__ void mma8(float* c, const uint32_t* a, const uint32_t* b) {
    asm volatile(
        "mma.sync.aligned.m16n8k8.row.col.f32.tf32.tf32.f32 "
        "{%0,%1,%2,%3}, {%4,%5,%6,%7}, {%8,%9}, {%0,%1,%2,%3};"
        : "+f"(c[0]), "+f"(c[1]), "+f"(c[2]), "+f"(c[3])
        : "r"(a[0]), "r"(a[1]), "r"(a[2]), "r"(a[3]), "r"(b[0]), "r"(b[1]));
}

// Split-tile format (both A and B operands):
//   tile = one (128 rows x 32 k) block = 2048 float4 = 32 KB.
//   float4 index within tile: (kb*128 + row)*4 + tg, kb = k8-block (0..3),
//   tg = k&3; float4 = {hi(k=kb*8+tg), lo, hi(k=kb*8+tg+4), lo}.
//   A half-tile (kb 0..1 / 2..3) is a contiguous 1024-float4 block.
#define TF4 2048

__device__ __forceinline__ void split_store(float2* base, size_t tile, int row, int k, float v) {
    int idx4 = ((((k >> 3) & 3) * 128 + row) << 2) + (k & 3);
    base[tile * (TF4 * 2) + idx4 * 2 + ((k >> 2) & 1)] = split2(v);
}

// ============================ tf32x3 GEMM (pre-split tiles) ==================
// C[M,N] = A @ B^T from pre-split tiles. 128x128 CTA, 8 warps 4x2, BK=16/stage,
// 3-stage ring (96 KB) -> 2 CTAs/SM.
// MODE 0: +bias[n].  MODE 1: +bias, also writes G3-A split tiles (G2).
// MODE 2: +aux[(row & 8191)*N + n]  (G3 row-permuted broadcast add).
#define SMEM_DYN (3 * 32 * 1024)

template<int MODE>
__global__ void __launch_bounds__(256, 2) mma_gemm(
    const float4* __restrict__ At, int nAk,
    const float4* __restrict__ Bt, int nBk, int koff, int nhk,   // nhk = # half-tiles
    const float* __restrict__ aux, float* __restrict__ C, int N,
    float2* __restrict__ sp)
{
    extern __shared__ float4 sm4[];          // 3 bufs x 2048 float4 (A 1024 | B 1024)
    const int tid  = threadIdx.x;
    const int lane = tid & 31, wid = tid >> 5;
    const int wm = wid & 3, wn = wid >> 2;
    const int g = lane >> 2, tg = lane & 3;
    const int bm = blockIdx.x * 128, bn = blockIdx.y * 128;

    float acc[2][8][4];
    #pragma unroll
    for (int mt = 0; mt < 2; mt++)
        #pragma unroll
        for (int nt = 0; nt < 8; nt++)
            #pragma unroll
            for (int i = 0; i < 4; i++) acc[mt][nt][i] = 0.f;

    // half-tile hk -> A float4 offset hk*1024 within this block-row's tiles
    const float4* Ab = At + (size_t)blockIdx.x * nAk * TF4 + tid;
    const float4* Bb = Bt + ((size_t)blockIdx.y * nBk + koff) * TF4 + tid;

    auto load_stage = [&](int hk, int buf) {
        const float4* a = Ab + (size_t)hk * 1024;
        const float4* b = Bb + (size_t)hk * 1024;
        uint32_t d = smem_u32(&sm4[buf * 2048 + tid]);
        #pragma unroll
        for (int i = 0; i < 4; i++) cp_async16(d + i * 4096, a + i * 256);
        d += 1024 * 16;
        #pragma unroll
        for (int i = 0; i < 4; i++) cp_async16(d + i * 4096, b + i * 256);
    };

    load_stage(0, 0); cp_commit();
    load_stage(1, 1); cp_commit();

    for (int it = 0; it < nhk; it++) {
        cp_wait<1>();
        __syncthreads();
        if (it + 2 < nhk) load_stage(it + 2, (it + 2) % 3);
        cp_commit();

        const float4* sA = &sm4[(it % 3) * 2048];
        const float4* sB = sA + 1024;
        #pragma unroll
        for (int kb = 0; kb < 2; kb++) {
            uint32_t aH[2][4], aL[2][4];
            #pragma unroll
            for (int mt = 0; mt < 2; mt++) {
                const int rr = wm * 32 + mt * 16 + g;
                float4 v0 = sA[((kb * 128 + rr)     << 2) + tg];
                float4 v1 = sA[((kb * 128 + rr + 8) << 2) + tg];
                aH[mt][0] = __float_as_uint(v0.x); aH[mt][1] = __float_as_uint(v1.x);
                aH[mt][2] = __float_as_uint(v0.z); aH[mt][3] = __float_as_uint(v1.z);
                aL[mt][0] = __float_as_uint(v0.y); aL[mt][1] = __float_as_uint(v1.y);
                aL[mt][2] = __float_as_uint(v0.w); aL[mt][3] = __float_as_uint(v1.w);
            }
            #pragma unroll
            for (int nh = 0; nh < 2; nh++) {
                uint32_t bH[4][2], bL[4][2];
                #pragma unroll
                for (int q = 0; q < 4; q++) {
                    const int n = wn * 64 + (nh * 4 + q) * 8 + g;
                    float4 w = sB[((kb * 128 + n) << 2) + tg];
                    bH[q][0] = __float_as_uint(w.x); bH[q][1] = __float_as_uint(w.z);
                    bL[q][0] = __float_as_uint(w.y); bL[q][1] = __float_as_uint(w.w);
                }
                float* a0 = &acc[0][nh * 4][0];
                float* a1 = &acc[1][nh * 4][0];
                #pragma unroll
                for (int q = 0; q < 4; q++) { mma8(a0 + q * 4, aH[0], bL[q]); mma8(a1 + q * 4, aH[1], bL[q]); }
                #pragma unroll
                for (int q = 0; q < 4; q++) { mma8(a0 + q * 4, aL[0], bH[q]); mma8(a1 + q * 4, aL[1], bH[q]); }
                #pragma unroll
                for (int q = 0; q < 4; q++) { mma8(a0 + q * 4, aH[0], bH[q]); mma8(a1 + q * 4, aH[1], bH[q]); }
            }
        }
    }

    // ---------------- epilogue --------------------------------------------
    #pragma unroll
    for (int mt = 0; mt < 2; mt++) {
        const int row0 = bm + wm * 32 + mt * 16 + g;
        #pragma unroll
        for (int nt = 0; nt < 8; nt++) {
            const int col = bn + wn * 64 + nt * 8 + 2 * tg;
            float o0 = acc[mt][nt][0], o1 = acc[mt][nt][1];
            float o2 = acc[mt][nt][2], o3 = acc[mt][nt][3];
            if (MODE != 2) {
                float z0 = aux[col], z1 = aux[col + 1];
                o0 += z0; o1 += z1; o2 += z0; o3 += z1;
            } else {
                const float* a0 = aux + (size_t)(row0 & (BATCH - 1)) * N + col;
                const float* a1 = aux + (size_t)((row0 + 8) & (BATCH - 1)) * N + col;
                o0 += a0[0]; o1 += a0[1]; o2 += a1[0]; o3 += a1[1];
            }
            *(float2*)(C + (size_t)row0 * N + col)       = make_float2(o0, o1);
            *(float2*)(C + (size_t)(row0 + 8) * N + col) = make_float2(o2, o3);
            if (MODE == 1) {
                // write hyps as G3-A split tiles, permuted row r = k*8192 + b
                #pragma unroll
                for (int q = 0; q < 4; q++) {
                    int b = row0 + (q >> 1) * 8;
                    int c = col + (q & 1);
                    float v = (q == 0) ? o0 : (q == 1) ? o1 : (q == 2) ? o2 : o3;
                    int kk = c >> 10, h = c & 1023;
                    int r = kk * BATCH + b;
                    split_store(sp, (size_t)(r >> 7) * 32 + (h >> 5), r & 127, h & 31, v);
                }
            }
        }
    }
}

// ================= one-time weight transpose+split+tile ======================
// W [K][N] row-major  ->  B-split tiles [nblk][kblk], nBk = K/32 tiles per nblk.
__global__ void __launch_bounds__(256) wsplit_kernel(
    const float* __restrict__ W, float2* __restrict__ out, int N)
{
    __shared__ float s[32 * 132];
    const int t = threadIdx.x;
    #pragma unroll
    for (int i = 0; i < 16; i++) {
        int e = t + i * 256;
        int kl = e >> 7, nl = e & 127;
        s[kl * 132 + nl] = W[(size_t)(blockIdx.y * 32 + kl) * N + blockIdx.x * 128 + nl];
    }
    __syncthreads();
    float2* ob = out + ((size_t)blockIdx.x * gridDim.y + blockIdx.y) * (TF4 * 2);
    #pragma unroll
    for (int i = 0; i < 16; i++) {
        int o = t + i * 256;                 // float2 slot within tile
        int idx4 = o >> 1, half = o & 1;
        int tg = idx4 & 3, nl = (idx4 >> 2) & 127, kb = idx4 >> 9;
        int kl = kb * 8 + half * 4 + tg;
        ob[o] = split2(s[kl * 132 + nl]);
    }
}

// ================= x -> A-split tiles ========================================
__global__ void __launch_bounds__(256) xsplit_kernel(
    const float* __restrict__ x, float2* __restrict__ out)
{
    const int m = blockIdx.x;
    const float* p = x + (size_t)m * HD;
    #pragma unroll
    for (int i = 0; i < 4; i++) {
        int j = threadIdx.x + i * 256;
        split_store(out, (size_t)(m >> 7) * 32 + (j >> 5), m & 127, j & 31, p[j]);
    }
}

// ---------------- block reduction of two scalars (256 threads) --------------
__device__ __forceinline__ void block_reduce2(float& a, float& b) {
    __shared__ float sa[8], sb[8];
    float x = a, y = b;
    #pragma unroll
    for (int o = 16; o > 0; o >>= 1) {
        x += __shfl_down_sync(0xffffffffu, x, o);
        y += __shfl_down_sync(0xffffffffu, y, o);
    }
    int w = threadIdx.x >> 5;
    if ((threadIdx.x & 31) == 0) { sa[w] = x; sb[w] = y; }
    __syncthreads();
    if (threadIdx.x == 0) {
        float xs = 0.f, ys = 0.f;
        #pragma unroll
        for (int i = 0; i < 8; i++) { xs += sa[i]; ys += sb[i]; }
        sa[0] = xs; sb[0] = ys;
    }
    __syncthreads();
    a = sa[0]; b = sb[0];
    __syncthreads();
}

// -------- LN + ReLU over width 2048, writes h as A-split tiles (nAk=64) -----
__global__ void __launch_bounds__(256) ln_relu_split(
    const float* __restrict__ y, const float* __restrict__ g,
    const float* __restrict__ beta, float2* __restrict__ hs)
{
    const int row = blockIdx.x;
    const float* p = y + (size_t)row * 2048;
    const int t = threadIdx.x;
    float v[8];
    float s = 0.f, ss = 0.f;
    #pragma unroll
    for (int i = 0; i < 8; i++) {
        v[i] = p[t + i * 256];
        s += v[i]; ss += v[i] * v[i];
    }
    block_reduce2(s, ss);
    const float mean = s * (1.f / 2048.f);
    const float var  = ss * (1.f / 2048.f) - mean * mean;
    const float rs   = rsqrtf(var + EPSLN);
    #pragma unroll
    for (int i = 0; i < 8; i++) {
        int j = t + i * 256;
        float o = fmaxf((v[i] - mean) * rs * g[j] + beta[j], 0.f);
        split_store(hs, (size_t)(row >> 7) * 64 + (j >> 5), row & 127, j & 31, o);
    }
}

// ---------------- per permuted row: LN + ReLU + dot(We2) + sigmoid ----------
__global__ void __launch_bounds__(256) score_kernel(
    const float* __restrict__ e, const float* __restrict__ ge,
    const float* __restrict__ betae, const float* __restrict__ We2,
    const float* __restrict__ be2, float* __restrict__ scores)
{
    const int r = blockIdx.x;               // r = k*8192 + b
    const float* p = e + (size_t)r * HD;
    const int t = threadIdx.x;
    float v[4];
    float s = 0.f, ss = 0.f;
    #pragma unroll
    for (int i = 0; i < 4; i++) {
        v[i] = p[t + i * 256];
        s += v[i]; ss += v[i] * v[i];
    }
    block_reduce2(s, ss);
    const float mean = s * (1.f / 1024.f);
    const float var  = ss * (1.f / 1024.f) - mean * mean;
    const float rs   = rsqrtf(var + EPSLN);
    float d = 0.f, dummy = 0.f;
    #pragma unroll
    for (int i = 0; i < 4; i++) {
        int j = t + i * 256;
        float o = fmaxf((v[i] - mean) * rs * ge[j] + betae[j], 0.f);
        d = fmaf(o, We2[j], d);
    }
    block_reduce2(d, dummy);
    if (t == 0) {
        int b = r & (BATCH - 1), k = r >> 13;
        scores[(size_t)b * KH + k] = 1.f / (1.f + expf(-(d + be2[0])));
    }
}

// ---------------- argmax over K, gather best hypothesis ---------------------
__global__ void __launch_bounds__(128) finalize_kernel(
    const float* __restrict__ scores, const float* __restrict__ hyps,
    float* __restrict__ best_hyp, float* __restrict__ best_idx,
    float* __restrict__ best_sc)
{
    const int b = blockIdx.x;
    __shared__ int sidx;
    if (threadIdx.x == 0) {
        const float* sc = scores + (size_t)b * KH;
        int bi = 0; float bv = sc[0];
        #pragma unroll
        for (int k = 1; k < KH; k++)
            if (sc[k] > bv) { bv = sc[k]; bi = k; }
        sidx = bi;
        best_idx[b] = (float)bi;
        best_sc[b]  = bv;
    }
    __syncthreads();
    const float* src = hyps + ((size_t)b * KH + sidx) * HD;
    float* dst = best_hyp + (size_t)b * HD;
    #pragma unroll
    for (int i = 0; i < HD / 128; i++)
        dst[threadIdx.x + i * 128] = src[threadIdx.x + i * 128];
}

// ---------------- launcher ---------------------------------------------------
extern "C" void kernel_launch(void* const* d_in, const int* in_sizes, int n_in,
                              void* d_out, int out_size)
{
    const float* x     = (const float*)d_in[0];
    const float* W1    = (const float*)d_in[1];
    const float* b1    = (const float*)d_in[2];
    const float* g1    = (const float*)d_in[3];
    const float* beta1 = (const float*)d_in[4];
    const float* W2    = (const float*)d_in[5];
    const float* b2    = (const float*)d_in[6];
    const float* We1   = (const float*)d_in[7];
    const float* be1   = (const float*)d_in[8];
    const float* ge    = (const float*)d_in[9];
    const float* betae = (const float*)d_in[10];
    const float* We2   = (const float*)d_in[11];
    const float* be2   = (const float*)d_in[12];

    float* out = (float*)d_out;
    float* out_best_hyp = out;                                    // [B, H]
    float* out_hyps     = out + (size_t)BATCH * HD;               // [B, K, H]
    float* out_scores   = out_hyps + (size_t)BATCH * KH * HD;     // [B, K]
    float* out_best_idx = out_scores + (size_t)BATCH * KH;        // [B, 1]
    float* out_best_sc  = out_best_idx + BATCH;                   // [B, 1]

    float *y1, *xe, *e;
    float2 *xs, *hs, *as, *w1s, *w2s, *we1s;
    cudaGetSymbolAddress((void**)&y1,   g_y1);
    cudaGetSymbolAddress((void**)&xe,   g_xe);
    cudaGetSymbolAddress((void**)&e,    g_e);
    cudaGetSymbolAddress((void**)&xs,   g_xs);
    cudaGetSymbolAddress((void**)&hs,   g_hs);
    cudaGetSymbolAddress((void**)&as,   g_as);
    cudaGetSymbolAddress((void**)&w1s,  g_w1s);
    cudaGetSymbolAddress((void**)&w2s,  g_w2s);
    cudaGetSymbolAddress((void**)&we1s, g_we1s);

    cudaFuncSetAttribute(mma_gemm<0>, cudaFuncAttributeMaxDynamicSharedMemorySize, SMEM_DYN);
    cudaFuncSetAttribute(mma_gemm<1>, cudaFuncAttributeMaxDynamicSharedMemorySize, SMEM_DYN);
    cudaFuncSetAttribute(mma_gemm<2>, cudaFuncAttributeMaxDynamicSharedMemorySize, SMEM_DYN);

    // weight split tiles: W [K][N] -> [nblk][kblk]
    wsplit_kernel<<<dim3(2 * HD / 128, HD / 32),      256>>>(W1,  w1s,  2 * HD);  // nBk=32
    wsplit_kernel<<<dim3(KH * HD / 128, 2 * HD / 32), 256>>>(W2,  w2s,  KH * HD); // nBk=64
    wsplit_kernel<<<dim3(HD / 128, 2 * HD / 32),      256>>>(We1, we1s, HD);      // nBk=64

    // x split tiles (nAk=32)
    xsplit_kernel<<<BATCH, 256>>>(x, xs);

    // G1: y1 = x @ W1 + b1                       [8192, 2048], K=1024 (64 half-tiles)
    mma_gemm<0><<<dim3(BATCH / 128, 2 * HD / 128), 256, SMEM_DYN>>>(
        (const float4*)xs, 32, (const float4*)w1s, 32, 0, 64, b1, y1, 2 * HD, nullptr);

    // GX: xe = x @ We1[0:H,:] + be1              [8192, 1024], K=1024
    mma_gemm<0><<<dim3(BATCH / 128, HD / 128), 256, SMEM_DYN>>>(
        (const float4*)xs, 32, (const float4*)we1s, 64, 0, 64, be1, xe, HD, nullptr);

    // LN + ReLU -> h split tiles (nAk=64)
    ln_relu_split<<<BATCH, 256>>>(y1, g1, beta1, hs);

    // G2: hyps = h @ W2 + b2                     [8192, 8192], K=2048 (128 half-tiles)
    mma_gemm<1><<<dim3(BATCH / 128, KH * HD / 128), 256, SMEM_DYN>>>(
        (const float4*)hs, 64, (const float4*)w2s, 64, 0, 128, b2, out_hyps, KH * HD, as);

    // G3: e[r] = hyps_perm @ We1[H:2H,:] + xe[b] [65536, 1024], K=1024
    mma_gemm<2><<<dim3(BATCH * KH / 128, HD / 128), 256, SMEM_DYN>>>(
        (const float4*)as, 32, (const float4*)we1s, 64, 32, 64, xe, e, HD, nullptr);

    // scores = sigmoid(relu(LN(e)) . We2 + be2)
    score_kernel<<<BATCH * KH, 256>>>(e, ge, betae, We2, be2, out_scores);

    // argmax / gather
    finalize_kernel<<<BATCH, 128>>>(out_scores, out_hyps,
                                    out_best_hyp, out_best_idx, out_best_sc);
}